// round 17
// baseline (speedup 1.0000x reference)
#include <cuda_runtime.h>
#include <cuda_bf16.h>
#include <cuda_fp8.h>
#include <cstdint>

#define PP 1024
#define NROW 16384
#define TILE_M 128
#define TILE_N 64
#define KC 64
#define NBN (PP / TILE_N)      // 16 n-tiles
#define NSLOT NBN              // 1 ypart slot per n-tile

// smem stage layout (bytes)
#define AHI 0                  // bf16 128x64   16KB
#define AQ  16384              // e4m3 128x64    8KB
#define ALO 24576              // e4m3 128x64    8KB
#define BHI 32768              // bf16 64x64     8KB
#define BQ  40960              // e4m3 64x64     4KB
#define BLO 45056              // e4m3 64x64     4KB
#define STAGE_BYTES 49152
#define SMEM_TOTAL (2 * STAGE_BYTES)   // 96 KB -> 2 CTAs/SM

// prep kernel split point: X-blocks (8 floats/thread) then W-blocks
#define XBLK (NROW * PP / 8 / 256)     // 8192
#define WBLK (PP * PP / 4 / 256)       // 1024

// Scratch (static __device__ — no allocation allowed)
__device__ __align__(16) __nv_bfloat16 g_Xhi[(size_t)NROW * PP];
__device__ __align__(16) unsigned char g_Xq[(size_t)NROW * PP];   // e4m3(x)
__device__ __align__(16) unsigned char g_Xlo[(size_t)NROW * PP];  // e4m3(256*(x-hi))
__device__ __align__(16) __nv_bfloat16 g_Whi[(size_t)PP * PP];    // W^T [n][k]
__device__ __align__(16) unsigned char g_Wq[(size_t)PP * PP];
__device__ __align__(16) unsigned char g_Wlo[(size_t)PP * PP];
__device__ float g_ypart[(size_t)NSLOT * NROW];

// ---------------- helpers ----------------
__device__ __forceinline__ uint32_t smem_u32(const void* p) {
    uint32_t a;
    asm("{ .reg .u64 t; cvta.to.shared.u64 t, %1; cvt.u32.u64 %0, t; }" : "=r"(a) : "l"(p));
    return a;
}
// bf16 tiles: 128B rows; 16B chunk swizzle: chunk ^= (row & 7)
__device__ __forceinline__ uint32_t sw(int row, int ch) {
    return (uint32_t)(row * 128 + ((ch ^ (row & 7)) << 4));
}
// fp8 tiles: 64B rows; 16B chunk swizzle: chunk ^= ((row>>1) & 3)
__device__ __forceinline__ uint32_t sw8(int row, int ch) {
    return (uint32_t)(row * 64 + ((ch ^ ((row >> 1) & 3)) << 4));
}
__device__ __forceinline__ void cp16(uint32_t dst, const void* src) {
    asm volatile("cp.async.cg.shared.global [%0], [%1], 16;" :: "r"(dst), "l"(src) : "memory");
}
__device__ __forceinline__ void ldmx4(uint32_t* r, uint32_t addr) {
    asm volatile("ldmatrix.sync.aligned.m8n8.x4.shared.b16 {%0,%1,%2,%3}, [%4];"
                 : "=r"(r[0]), "=r"(r[1]), "=r"(r[2]), "=r"(r[3]) : "r"(addr));
}
__device__ __forceinline__ void mma16816(float* c, const uint32_t* a, const uint32_t* b) {
    asm volatile(
        "mma.sync.aligned.m16n8k16.row.col.f32.bf16.bf16.f32 "
        "{%0,%1,%2,%3}, {%4,%5,%6,%7}, {%8,%9}, {%0,%1,%2,%3};"
        : "+f"(c[0]), "+f"(c[1]), "+f"(c[2]), "+f"(c[3])
        : "r"(a[0]), "r"(a[1]), "r"(a[2]), "r"(a[3]), "r"(b[0]), "r"(b[1]));
}
__device__ __forceinline__ void mma16832f8(float* c, const uint32_t* a, const uint32_t* b) {
    asm volatile(
        "mma.sync.aligned.m16n8k32.row.col.f32.e4m3.e4m3.f32 "
        "{%0,%1,%2,%3}, {%4,%5,%6,%7}, {%8,%9}, {%0,%1,%2,%3};"
        : "+f"(c[0]), "+f"(c[1]), "+f"(c[2]), "+f"(c[3])
        : "r"(a[0]), "r"(a[1]), "r"(a[2]), "r"(a[3]), "r"(b[0]), "r"(b[1]));
}
__device__ __forceinline__ unsigned char f2e4m3(float f) {
    return (unsigned char)__nv_cvt_float_to_fp8(f, __NV_SATFINITE, __NV_E4M3);
}

// ---------------------------------------------------------------------------
// Fused prep: blocks [0, XBLK) split X (8 floats/thread) into bf16 hi +
// e4m3(x) + e4m3(256*lo); blocks [XBLK, ..) build W^T the same way.
// ---------------------------------------------------------------------------
__global__ void prep_kernel(const float* __restrict__ X,
                            const float* __restrict__ theta) {
    if (blockIdx.x < XBLK) {
        size_t idx = (size_t)blockIdx.x * 256 + threadIdx.x;   // over N*P/8
        float4 v0 = reinterpret_cast<const float4*>(X)[idx * 2];
        float4 v1 = reinterpret_cast<const float4*>(X)[idx * 2 + 1];
        float f[8] = {v0.x, v0.y, v0.z, v0.w, v1.x, v1.y, v1.z, v1.w};
        uint32_t hi[4];
        unsigned char q[8], lo8[8];
#pragma unroll
        for (int e = 0; e < 8; ++e) {
            __nv_bfloat16 h = __float2bfloat16(f[e]);
            float r = f[e] - __bfloat162float(h);
            q[e] = f2e4m3(f[e]);
            lo8[e] = f2e4m3(r * 256.0f);
            if (e & 1)
                hi[e >> 1] |= (uint32_t)__bfloat16_as_ushort(h) << 16;
            else
                hi[e >> 1] = (uint32_t)__bfloat16_as_ushort(h);
        }
        reinterpret_cast<uint4*>(g_Xhi)[idx] = make_uint4(hi[0], hi[1], hi[2], hi[3]);
        uint32_t qa = q[0] | (q[1] << 8) | (q[2] << 16) | ((uint32_t)q[3] << 24);
        uint32_t qb = q[4] | (q[5] << 8) | (q[6] << 16) | ((uint32_t)q[7] << 24);
        uint32_t la = lo8[0] | (lo8[1] << 8) | (lo8[2] << 16) | ((uint32_t)lo8[3] << 24);
        uint32_t lb = lo8[4] | (lo8[5] << 8) | (lo8[6] << 16) | ((uint32_t)lo8[7] << 24);
        reinterpret_cast<uint2*>(g_Xq)[idx] = make_uint2(qa, qb);
        reinterpret_cast<uint2*>(g_Xlo)[idx] = make_uint2(la, lb);
    } else {
        int idx4 = (int)(blockIdx.x - XBLK) * 256 + threadIdx.x;  // over P*P/4
        int base = idx4 * 4;
        int n = base >> 10;
        int k0 = base & (PP - 1);     // 4 consecutive k, same n
        uint32_t hi[2];
        unsigned char q[4], lo8[4];
#pragma unroll
        for (int e = 0; e < 4; ++e) {
            int k = k0 + e;
            float v = (n > k) ? theta[k * PP - ((k * (k + 1)) >> 1) + (n - k - 1)] : 0.0f;
            __nv_bfloat16 h = __float2bfloat16(v);
            float r = v - __bfloat162float(h);
            q[e] = f2e4m3(v);
            lo8[e] = f2e4m3(r * 256.0f);
            if (e & 1)
                hi[e >> 1] |= (uint32_t)__bfloat16_as_ushort(h) << 16;
            else
                hi[e >> 1] = (uint32_t)__bfloat16_as_ushort(h);
        }
        reinterpret_cast<uint2*>(g_Whi + base)[0] = make_uint2(hi[0], hi[1]);
        reinterpret_cast<uint32_t*>(g_Wq + base)[0] =
            q[0] | (q[1] << 8) | (q[2] << 16) | ((uint32_t)q[3] << 24);
        reinterpret_cast<uint32_t*>(g_Wlo + base)[0] =
            lo8[0] | (lo8[1] << 8) | (lo8[2] << 16) | ((uint32_t)lo8[3] << 24);
    }
}

// ---------------------------------------------------------------------------
// Main: mixed bf16/fp8 GEMM (128x64 tile, 2 CTAs/SM, 4m x 2n warp grid).
// T1 = Xhi·Whi (bf16 k16 MMAs); T2 = e4m3(x)·e4m3(256 Wlo), T3 =
// e4m3(256 Xlo)·e4m3(w) (fp8 k32 MMAs into acc2, dequant 2^-8 in epilogue).
// Triangular skip nch_eff = bn+1; LPT heavy-first; one __syncthreads/chunk.
// ---------------------------------------------------------------------------
__global__ __launch_bounds__(256, 2)
void gemm_rowdot_mma(const float* __restrict__ X, const float* __restrict__ beta) {
    extern __shared__ char smem[];
    const uint32_t sbase = smem_u32(smem);
    const int tid = threadIdx.x;
    const int l = tid & 31;
    const int wid = tid >> 5;
    const int wm = wid & 3;        // 4 m-warps (32 rows each)
    const int wn = wid >> 2;       // 2 n-warps (32 cols each)
    const int m_base = wm * 32;
    const int n_base = wn * 32;

    const int bn = (NBN - 1) - (int)(blockIdx.x >> 7);
    const int bx = (int)(blockIdx.x & 127);
    const int i0 = bx * TILE_M;
    const int n0 = bn * TILE_N;
    const int nch_eff = bn + 1;

    // bf16 fragment addressing
    const int a_r  = l & 15;
    const int a_kh = l >> 4;
    const int b_nr = ((l >> 4) << 3) + (l & 7);
    const int b_kh = (l >> 3) & 1;
    // fp8 fragment addressing (ldmx4 tile groups)
    const int g8    = l >> 3;
    const int f8_r  = ((g8 & 1) << 3) + (l & 7);  // A row within 16
    const int f8_h  = g8 >> 1;                    // A 16B half within k32

    float acc[2][4][4], acc2[2][4][4];
#pragma unroll
    for (int mi = 0; mi < 2; ++mi)
#pragma unroll
        for (int ni = 0; ni < 4; ++ni)
#pragma unroll
            for (int q = 0; q < 4; ++q) { acc[mi][ni][q] = 0.0f; acc2[mi][ni][q] = 0.0f; }

    auto load_stage = [&](int c) {
        const uint32_t stg = sbase + (uint32_t)(c & 1) * STAGE_BYTES;
        const int k0 = c * KC;
        // Ahi bf16: 1024 chunks
#pragma unroll
        for (int it = 0; it < 4; ++it) {
            int u = tid + it * 256;
            int row = u >> 3, ch = u & 7;
            cp16(stg + AHI + sw(row, ch), g_Xhi + (size_t)(i0 + row) * PP + k0 + ch * 8);
        }
        // Aq / Alo fp8: 512 chunks each
#pragma unroll
        for (int it = 0; it < 2; ++it) {
            int u = tid + it * 256;
            int row = u >> 2, ch = u & 3;
            uint32_t d = sw8(row, ch);
            size_t src = (size_t)(i0 + row) * PP + k0 + ch * 16;
            cp16(stg + AQ + d, g_Xq + src);
            cp16(stg + ALO + d, g_Xlo + src);
        }
        // Bhi bf16: 512 chunks
#pragma unroll
        for (int it = 0; it < 2; ++it) {
            int u = tid + it * 256;
            int row = u >> 3, ch = u & 7;
            cp16(stg + BHI + sw(row, ch), g_Whi + (size_t)(n0 + row) * PP + k0 + ch * 8);
        }
        // Bq / Blo fp8: 256 chunks each
        {
            int row = tid >> 2, ch = tid & 3;
            uint32_t d = sw8(row, ch);
            size_t src = (size_t)(n0 + row) * PP + k0 + ch * 16;
            cp16(stg + BQ + d, g_Wq + src);
            cp16(stg + BLO + d, g_Wlo + src);
        }
        asm volatile("cp.async.commit_group;" ::: "memory");
    };

    load_stage(0);

    for (int c = 0; c < nch_eff; ++c) {
        asm volatile("cp.async.wait_group 0;" ::: "memory");
        __syncthreads();
        if (c + 1 < nch_eff) load_stage(c + 1);

        const uint32_t stg = sbase + (uint32_t)(c & 1) * STAGE_BYTES;

        // ---- T1: bf16 hi x hi ----
#pragma unroll
        for (int ks = 0; ks < 4; ++ks) {
            uint32_t ahi[2][4], bhi[4][2];
            int cha = ks * 2 + a_kh;
#pragma unroll
            for (int mi = 0; mi < 2; ++mi)
                ldmx4(ahi[mi], stg + AHI + sw(m_base + mi * 16 + a_r, cha));
            int chb = ks * 2 + b_kh;
#pragma unroll
            for (int np = 0; np < 2; ++np) {
                uint32_t r4[4];
                ldmx4(r4, stg + BHI + sw(n_base + np * 16 + b_nr, chb));
                bhi[np * 2][0] = r4[0]; bhi[np * 2][1] = r4[1];
                bhi[np * 2 + 1][0] = r4[2]; bhi[np * 2 + 1][1] = r4[3];
            }
#pragma unroll
            for (int mi = 0; mi < 2; ++mi)
#pragma unroll
                for (int ni = 0; ni < 4; ++ni)
                    mma16816(acc[mi][ni], ahi[mi], bhi[ni]);
        }

        // ---- T2+T3: fp8 corrections (k32 steps) ----
#pragma unroll
        for (int s = 0; s < 2; ++s) {
            uint32_t aq[2][4], alo[2][4], bq[4][2], blo[4][2];
#pragma unroll
            for (int mi = 0; mi < 2; ++mi) {
                uint32_t ad = sw8(m_base + mi * 16 + f8_r, 2 * s + f8_h);
                ldmx4(aq[mi], stg + AQ + ad);
                ldmx4(alo[mi], stg + ALO + ad);
            }
#pragma unroll
            for (int np = 0; np < 2; ++np) {
                uint32_t bd = sw8(n_base + np * 16 + b_nr, 2 * s + b_kh);
                uint32_t r4[4];
                ldmx4(r4, stg + BQ + bd);
                bq[np * 2][0] = r4[0]; bq[np * 2][1] = r4[1];
                bq[np * 2 + 1][0] = r4[2]; bq[np * 2 + 1][1] = r4[3];
                ldmx4(r4, stg + BLO + bd);
                blo[np * 2][0] = r4[0]; blo[np * 2][1] = r4[1];
                blo[np * 2 + 1][0] = r4[2]; blo[np * 2 + 1][1] = r4[3];
            }
#pragma unroll
            for (int mi = 0; mi < 2; ++mi)
#pragma unroll
                for (int ni = 0; ni < 4; ++ni) {
                    mma16832f8(acc2[mi][ni], aq[mi], blo[ni]);   // x * 256*Wlo
                    mma16832f8(acc2[mi][ni], alo[mi], bq[ni]);   // 256*Xlo * w
                }
        }
    }
    __syncthreads();

    // --- fused epilogue: part_r = sum_c (C[r][c] + beta[c]) * X[r][c] ---
    const float DEQ = 0.00390625f;   // 2^-8
    float* sarr = (float*)smem;      // 2*128 floats
#pragma unroll
    for (int mi = 0; mi < 2; ++mi) {
        int tr0 = m_base + mi * 16 + (l >> 2);
        int tr1 = tr0 + 8;
        int r0 = i0 + tr0;
        int r1 = i0 + tr1;
        float p0 = 0.0f, p1 = 0.0f;
#pragma unroll
        for (int ni = 0; ni < 4; ++ni) {
            int cc = n0 + n_base + ni * 8 + (l & 3) * 2;
            float2 bv  = *(const float2*)&beta[cc];
            float2 x0  = *(const float2*)&X[(size_t)r0 * PP + cc];
            float2 x1  = *(const float2*)&X[(size_t)r1 * PP + cc];
            float c0 = acc[mi][ni][0] + acc2[mi][ni][0] * DEQ;
            float c1 = acc[mi][ni][1] + acc2[mi][ni][1] * DEQ;
            float c2 = acc[mi][ni][2] + acc2[mi][ni][2] * DEQ;
            float c3 = acc[mi][ni][3] + acc2[mi][ni][3] * DEQ;
            p0 = fmaf(c0 + bv.x, x0.x, p0);
            p0 = fmaf(c1 + bv.y, x0.y, p0);
            p1 = fmaf(c2 + bv.x, x1.x, p1);
            p1 = fmaf(c3 + bv.y, x1.y, p1);
        }
        p0 += __shfl_xor_sync(0xffffffffu, p0, 1);
        p0 += __shfl_xor_sync(0xffffffffu, p0, 2);
        p1 += __shfl_xor_sync(0xffffffffu, p1, 1);
        p1 += __shfl_xor_sync(0xffffffffu, p1, 2);
        if ((l & 3) == 0) {
            sarr[wn * 128 + tr0] = p0;
            sarr[wn * 128 + tr1] = p1;
        }
    }
    __syncthreads();
    if (tid < 128) {
        float s = sarr[tid] + sarr[128 + tid];
        g_ypart[(size_t)bn * NROW + i0 + tid] = s;
    }
}

// ---------------------------------------------------------------------------
// Final: y[i] = beta0 + sum of 16 partials
// ---------------------------------------------------------------------------
__global__ void reduce_kernel(const float* __restrict__ beta0, float* __restrict__ y) {
    int i = blockIdx.x * blockDim.x + threadIdx.x;
    if (i >= NROW) return;
    float s = beta0[0];
#pragma unroll
    for (int g = 0; g < NSLOT; ++g) s += g_ypart[(size_t)g * NROW + i];
    y[i] = s;
}

extern "C" void kernel_launch(void* const* d_in, const int* in_sizes, int n_in,
                              void* d_out, int out_size) {
    const float* X     = (const float*)d_in[0];
    const float* beta0 = (const float*)d_in[1];
    const float* beta  = (const float*)d_in[2];
    const float* theta = (const float*)d_in[3];
    float* y = (float*)d_out;

    cudaFuncSetAttribute(gemm_rowdot_mma, cudaFuncAttributeMaxDynamicSharedMemorySize, SMEM_TOTAL);

    prep_kernel<<<XBLK + WBLK, 256>>>(X, theta);

    gemm_rowdot_mma<<<NBN * 128, 256, SMEM_TOTAL>>>(X, beta);

    reduce_kernel<<<(NROW + 255) / 256, 256>>>(beta0, y);
}